// round 11
// baseline (speedup 1.0000x reference)
#include <cuda_runtime.h>
#include <math.h>

// Problem constants
#define FS_F      100.0f
#define N_FILT    12
#define N_CH      27
#define KDIM      5
#define T_IN      65536
#define T_OUT     65532        // T_IN - KDIM + 1
#define TILE      2048
#define THREADS   256
#define N_TILES   32           // ceil(T_OUT / TILE)

__global__ __launch_bounds__(THREADS)
void sinc_conv_kernel(const float* __restrict__ x,
                      const float* __restrict__ filt_low,
                      const float* __restrict__ filt_band,
                      float* __restrict__ out)
{
    __shared__ float w[N_FILT][8];   // 5 taps per filter, padded

    const int blk  = blockIdx.x;
    const int tile = blk % N_TILES;
    const int bc   = blk / N_TILES;
    const int c    = bc % N_CH;
    const int b    = bc / N_CH;
    const int tid  = threadIdx.x;

    // ---- build the 12 filters for this channel (threads 0..11) ----
    if (tid < N_FILT) {
        const int f = tid;
        const float PI2 = 6.28318530717958647692f;

        float beg = fabsf(filt_low [c * N_FILT + f]) + 1.0f / FS_F;
        float end = beg + fabsf(filt_band[c * N_FILT + f]);

        // t_right = linspace(1,2,2)/FS = {0.01, 0.02}
        float aE1 = PI2 * FS_F * end * 0.01f;
        float aE2 = PI2 * FS_F * end * 0.02f;
        float aB1 = PI2 * FS_F * beg * 0.01f;
        float aB2 = PI2 * FS_F * beg * 0.02f;
        float yE1 = sinf(aE1) / aE1;
        float yE2 = sinf(aE2) / aE2;
        float yB1 = sinf(aB1) / aB1;
        float yB2 = sinf(aB2) / aB2;

        float e2 = 2.0f * end, b2 = 2.0f * beg;
        float bp0 = e2 * yE2 - b2 * yB2;   // outermost taps (symmetric)
        float bp1 = e2 * yE1 - b2 * yB1;
        float bp2 = e2        - b2;        // center (sinc(0)=1)

        float m = fmaxf(bp2, fmaxf(bp1, bp0));
        float inv_m = 1.0f / m;

        // Blackman-ish window, n = linspace(0, 5, 5) -> n_k = 1.25*k
        float win[KDIM];
        #pragma unroll
        for (int k = 0; k < KDIM; k++) {
            float n = 1.25f * (float)k;
            win[k] = 0.42f - 0.5f * cosf(PI2 * n / 5.0f)
                           + 0.08f * cosf(4.0f * PI2 * 0.5f * n / 5.0f);
        }
        // (identical value: 0.08*cos(4*pi*n/5) — kept algebraically same as before)
        #pragma unroll
        for (int k = 0; k < KDIM; k++) {
            float n = 1.25f * (float)k;
            win[k] = 0.42f - 0.5f * cosf(PI2 * n / 5.0f)
                           + 0.08f * cosf(2.0f * PI2 * n / 5.0f);
        }

        w[f][0] = bp0 * inv_m * win[0];
        w[f][1] = bp1 * inv_m * win[1];
        w[f][2] = bp2 * inv_m * win[2];
        w[f][3] = bp1 * inv_m * win[3];
        w[f][4] = bp0 * inv_m * win[4];
    }
    __syncthreads();

    const float* xrow = x + ((size_t)b * N_CH + c) * T_IN;
    float* orow       = out + ((size_t)(b * N_CH + c) * N_FILT) * T_OUT;

    // two groups of 4 outputs per thread; prefetch ALL input loads first (MLP=4)
    const int t0 = tile * TILE + tid * 4;            // group 0
    const int t1 = t0 + THREADS * 4;                 // group 1

    const bool p0 = (t0 <= T_OUT - 4);
    const bool p1 = (t1 <= T_OUT - 4);

    float4 a0, d0, a1, d1;
    if (p0) { a0 = __ldg((const float4*)(xrow + t0));
              d0 = __ldg((const float4*)(xrow + t0 + 4)); }
    if (p1) { a1 = __ldg((const float4*)(xrow + t1));
              d1 = __ldg((const float4*)(xrow + t1 + 4)); }

    const float x00 = a0.x, x01 = a0.y, x02 = a0.z, x03 = a0.w;
    const float x04 = d0.x, x05 = d0.y, x06 = d0.z, x07 = d0.w;
    const float x10 = a1.x, x11 = a1.y, x12 = a1.z, x13 = a1.w;
    const float x14 = d1.x, x15 = d1.y, x16 = d1.z, x17 = d1.w;

    float* ob0 = orow + t0;
    float* ob1 = orow + t1;

    // f-major store order: both groups' stores to row f issued back-to-back
    // (addresses 4KB apart in the same output row -> paired row visits)
    #pragma unroll
    for (int f = 0; f < N_FILT; f++) {
        const float c0 = w[f][0], c1 = w[f][1], c2 = w[f][2],
                    c3 = w[f][3], c4 = w[f][4];
        if (p0) {
            float4 o;
            o.x = fmaf(x00, c0, fmaf(x01, c1, fmaf(x02, c2, fmaf(x03, c3, x04 * c4))));
            o.y = fmaf(x01, c0, fmaf(x02, c1, fmaf(x03, c2, fmaf(x04, c3, x05 * c4))));
            o.z = fmaf(x02, c0, fmaf(x03, c1, fmaf(x04, c2, fmaf(x05, c3, x06 * c4))));
            o.w = fmaf(x03, c0, fmaf(x04, c1, fmaf(x05, c2, fmaf(x06, c3, x07 * c4))));
            *((float4*)(ob0 + (size_t)f * T_OUT)) = o;
        }
        if (p1) {
            float4 o;
            o.x = fmaf(x10, c0, fmaf(x11, c1, fmaf(x12, c2, fmaf(x13, c3, x14 * c4))));
            o.y = fmaf(x11, c0, fmaf(x12, c1, fmaf(x13, c2, fmaf(x14, c3, x15 * c4))));
            o.z = fmaf(x12, c0, fmaf(x13, c1, fmaf(x14, c2, fmaf(x15, c3, x16 * c4))));
            o.w = fmaf(x13, c0, fmaf(x14, c1, fmaf(x15, c2, fmaf(x16, c3, x17 * c4))));
            *((float4*)(ob1 + (size_t)f * T_OUT)) = o;
        }
    }
}

extern "C" void kernel_launch(void* const* d_in, const int* in_sizes, int n_in,
                              void* d_out, int out_size)
{
    const float* x         = (const float*)d_in[0];
    const float* filt_low  = (const float*)d_in[1];
    const float* filt_band = (const float*)d_in[2];
    float* out             = (float*)d_out;

    const int grid = 8 * N_CH * N_TILES;  // 6912 blocks, 2 blocks/SM resident
    sinc_conv_kernel<<<grid, THREADS>>>(x, filt_low, filt_band, out);
}